// round 7
// baseline (speedup 1.0000x reference)
#include <cuda_runtime.h>
#include <cstdint>

// DeepUDI, two kernels.
// K1 (attention): PERSISTENT, 1 CTA/SM, cross-tile double-buffered cp.async
//   pipeline: while computing tile t from buf[p], tile t+1's 80KB (w/qw/kw)
//   + hn gather stream into buf[p^1]. nb/x indices for tile t+1 ride in
//   tile t's commit group (they feed t+1's hn source addresses).
// K2 (GRU): unchanged (76% DRAM, near floor).

#define NN   2048
#define RR   2
#define KK   32
#define DD   64
#define FF   64
#define DD2  128
#define HPAD 68
#define NT   (NN * RR)

__device__ float df_g[NT * FF];   // 1MB scratch

__device__ __forceinline__ float sigm(float v) {
    return 1.f / (1.f + __expf(-v));
}

__device__ __forceinline__ void cp16(void* dst, const void* src) {
    uint32_t d = (uint32_t)__cvta_generic_to_shared(dst);
    asm volatile("cp.async.cg.shared.global [%0], [%1], 16;\n" :: "r"(d), "l"(src));
}
__device__ __forceinline__ void cp8(void* dst, const void* src) {
    uint32_t d = (uint32_t)__cvta_generic_to_shared(dst);
    asm volatile("cp.async.ca.shared.global [%0], [%1], 8;\n" :: "r"(d), "l"(src));
}
__device__ __forceinline__ void cp4(void* dst, const void* src) {
    uint32_t d = (uint32_t)__cvta_generic_to_shared(dst);
    asm volatile("cp.async.ca.shared.global [%0], [%1], 4;\n" :: "r"(d), "l"(src));
}
#define CP_COMMIT() asm volatile("cp.async.commit_group;\n" ::: "memory")
#define CP_WAIT0()  asm volatile("cp.async.wait_group 0;\n" ::: "memory")

struct Buf {
    float w[DD * FF];                    // 16KB
    float qw[FF * DD2];                  // 32KB
    float kw[FF * DD2];                  // 32KB
    float hn[KK][HPAD];                  // 8.5KB (hn, later Hn)
    float h[DD];                         // 256B
    __align__(16) char nbx[272];         // raw nb (<=256B) + raw x at +256
};
struct Smem {
    Buf   buf[2];
    float J[FF];
    float jqp[2][DD2];
    float v[FF];
    float sc[KK];
    int   flags[2];
};
#define ATTN_SMEM_BYTES ((int)sizeof(Smem))

// Issue the full load group for tile t into buf[q]; also fetch nb/x for
// tile tnn (t + stride) into buf[q^1].nbx (feeds the NEXT issue's hn).
__device__ __forceinline__ void issue_tile(Smem* S, int q, int t,
                                           int tnn_valid, int tnn, int idx64,
                                           int tid,
                                           const float* __restrict__ embed,
                                           const float* __restrict__ w,
                                           const float* __restrict__ qw,
                                           const float* __restrict__ kw,
                                           const void* __restrict__ nb_raw,
                                           const void* __restrict__ x_raw)
{
    Buf& B = S->buf[q];
    const long long nr = t;

    const float4* ws = (const float4*)(w + nr * (DD * FF));
    #pragma unroll
    for (int j = 0; j < 4; j++)
        cp16(((float4*)B.w) + tid + 256 * j, ws + tid + 256 * j);

    const float4* qs = (const float4*)(qw + nr * (FF * DD2));
    #pragma unroll
    for (int j = 0; j < 8; j++)
        cp16(((float4*)B.qw) + tid + 256 * j, qs + tid + 256 * j);

    const float4* ks = (const float4*)(kw + nr * (FF * DD2));
    #pragma unroll
    for (int j = 0; j < 8; j++)
        cp16(((float4*)B.kw) + tid + 256 * j, ks + tid + 256 * j);

    // hn gather: nb values for THIS tile are already in B.nbx
    #pragma unroll
    for (int j = 0; j < 2; j++) {
        int i2 = tid + 256 * j;
        int k  = i2 >> 4, dv = i2 & 15;
        long long nbi = idx64 ? ((const long long*)B.nbx)[k]
                              : (long long)((const int*)B.nbx)[k];
        cp16(&B.hn[k][dv * 4], embed + nbi * DD + dv * 4);
    }
    // center row h
    if (tid < 16) {
        long long xn = idx64 ? *(const long long*)(B.nbx + 256)
                             : (long long)*(const int*)(B.nbx + 256);
        cp16(&B.h[tid * 4], embed + xn * DD + tid * 4);
    }
    // nb/x for tile tnn -> other buffer's nbx
    if (tnn_valid) {
        char* NB = S->buf[q ^ 1].nbx;
        long long base = (long long)tnn * KK;
        if (idx64) {
            if (tid < 16) cp16(NB + tid * 16, (const char*)nb_raw + base * 8 + tid * 16);
            if (tid == 16) cp8(NB + 256, (const char*)x_raw + (long long)(tnn >> 1) * 8);
        } else {
            if (tid < 8)  cp16(NB + tid * 16, (const char*)nb_raw + base * 4 + tid * 16);
            if (tid == 8) cp4(NB + 256, (const char*)x_raw + (long long)(tnn >> 1) * 4);
        }
    }
    CP_COMMIT();
}

// ===================== Kernel 1: persistent attention ===================
__global__ __launch_bounds__(256, 1)
void attn_kernel(const void* __restrict__ x_raw,
                 const void* __restrict__ nb_raw,
                 const float* __restrict__ embed,
                 const float* __restrict__ w,
                 const float* __restrict__ qw,
                 const float* __restrict__ kw)
{
    extern __shared__ __align__(16) char smem_raw[];
    Smem* S = (Smem*)smem_raw;

    const int tid = threadIdx.x;
    const int bid = blockIdx.x;
    const int gsz = gridDim.x;

    // dtype detection (x = arange; int64 view has word[1]==0)
    if (tid == 0) {
        const int* xi = (const int*)x_raw;
        S->flags[0] = (xi[1] == 0) ? 1 : 0;
    }
    __syncthreads();
    const int idx64 = S->flags[0];

    // prologue: plain-load first tile's nb/x into buf[0].nbx
    const int t0 = bid;
    {
        char* NB = S->buf[0].nbx;
        long long base = (long long)t0 * KK;
        if (idx64) {
            if (tid < 64) ((int*)NB)[tid] = ((const int*)nb_raw)[base * 2 + tid];
            if (tid == 64) {
                ((int*)(NB + 256))[0] = ((const int*)x_raw)[(t0 >> 1) * 2];
                ((int*)(NB + 256))[1] = ((const int*)x_raw)[(t0 >> 1) * 2 + 1];
            }
        } else {
            if (tid < 32) ((int*)NB)[tid] = ((const int*)nb_raw)[base + tid];
            if (tid == 32) ((int*)(NB + 256))[0] = ((const int*)x_raw)[t0 >> 1];
        }
    }
    __syncthreads();

    issue_tile(S, 0, t0, (t0 + gsz) < NT, t0 + gsz, idx64, tid,
               embed, w, qw, kw, nb_raw, x_raw);

    const int k  = tid >> 3;
    const int g  = tid & 7;
    const int f0 = g * 8;

    int i = 0;
    for (int t = t0; t < NT; t += gsz, i++) {
        const int q = i & 1;
        CP_WAIT0();
        __syncthreads();

        const int tn = t + gsz;
        if (tn < NT)
            issue_tile(S, q ^ 1, tn, (tn + gsz) < NT, tn + gsz, idx64, tid,
                       embed, w, qw, kw, nb_raw, x_raw);

        Buf& B = S->buf[q];

        // ---- phase 1: Hn = hn @ w : thread = (k, f-octant) -------------
        float acc[8];
        #pragma unroll
        for (int j = 0; j < 8; j++) acc[j] = 0.f;

        #pragma unroll 4
        for (int d = 0; d < DD; d++) {
            float a = B.hn[k][d];
            float4 w0 = *(const float4*)&B.w[d * FF + f0];
            float4 w1 = *(const float4*)&B.w[d * FF + f0 + 4];
            acc[0] += a * w0.x; acc[1] += a * w0.y;
            acc[2] += a * w0.z; acc[3] += a * w0.w;
            acc[4] += a * w1.x; acc[5] += a * w1.y;
            acc[6] += a * w1.z; acc[7] += a * w1.w;
        }
        if (tid < FF) {
            float ja = 0.f;
            #pragma unroll 8
            for (int d = 0; d < DD; d++)
                ja += B.h[d] * B.w[d * FF + tid];
            S->J[tid] = ja;
        }
        __syncthreads();   // hn reads done; J published

        // overwrite hn with Hn
        *(float4*)&B.hn[k][f0]     = make_float4(acc[0], acc[1], acc[2], acc[3]);
        *(float4*)&B.hn[k][f0 + 4] = make_float4(acc[4], acc[5], acc[6], acc[7]);

        // ---- phase 2: Jq[e] = sum_f J[f]*qw[f,e] -----------------------
        {
            int e  = tid & 127;
            int fh = tid >> 7;
            float a2 = 0.f;
            #pragma unroll 8
            for (int f = fh * 32; f < fh * 32 + 32; f++)
                a2 += S->J[f] * B.qw[f * DD2 + e];
            S->jqp[fh][e] = a2;
        }
        __syncthreads();

        // ---- phase 3: v[f] = sum_e kw[f,e]*Jq[e] -----------------------
        {
            int warp = tid >> 5, lane = tid & 31;
            float4 q0 = ((const float4*)S->jqp[0])[lane];
            float4 q1 = ((const float4*)S->jqp[1])[lane];
            float4 qv = make_float4(q0.x + q1.x, q0.y + q1.y,
                                    q0.z + q1.z, q0.w + q1.w);
            #pragma unroll
            for (int ii = 0; ii < 8; ii++) {
                int f = warp * 8 + ii;
                float4 kv = *(const float4*)&B.kw[f * DD2 + lane * 4];
                float p = kv.x * qv.x + kv.y * qv.y + kv.z * qv.z + kv.w * qv.w;
                #pragma unroll
                for (int off = 16; off > 0; off >>= 1)
                    p += __shfl_xor_sync(0xffffffffu, p, off);
                if (lane == 0) S->v[f] = p;
            }
        }
        __syncthreads();

        // ---- phase 4: scores[k] = Hn[k,:].v ----------------------------
        {
            float s = 0.f;
            #pragma unroll
            for (int j = 0; j < 8; j++) s += acc[j] * S->v[f0 + j];
            s += __shfl_xor_sync(0xffffffffu, s, 1);
            s += __shfl_xor_sync(0xffffffffu, s, 2);
            s += __shfl_xor_sync(0xffffffffu, s, 4);
            if (g == 0) S->sc[k] = s;
        }
        __syncthreads();

        // ---- phase 5: softmax over K=32 (warp 0) -----------------------
        if (tid < 32) {
            float s = S->sc[tid];
            float m = s;
            #pragma unroll
            for (int off = 16; off > 0; off >>= 1)
                m = fmaxf(m, __shfl_xor_sync(0xffffffffu, m, off));
            float e = __expf(s - m);
            float sum = e;
            #pragma unroll
            for (int off = 16; off > 0; off >>= 1)
                sum += __shfl_xor_sync(0xffffffffu, sum, off);
            S->sc[tid] = e / sum;
        }
        __syncthreads();

        // ---- phase 6: df[f] = sum_k E[k]*Hn[k,f] -> scratch ------------
        if (tid < FF) {
            float da = 0.f;
            #pragma unroll
            for (int kk = 0; kk < KK; kk++)
                da += S->sc[kk] * B.hn[kk][tid];
            df_g[(long long)t * FF + tid] = da;
        }
        // no trailing sync needed: next iter's CP_WAIT0 + syncthreads
        // orders buffer reuse.
    }
}

// ===================== Kernel 2: GRU + combine (unchanged) ==============
__global__ __launch_bounds__(256)
void gru_kernel(const void* __restrict__ x_raw,
                const float* __restrict__ embed,
                const float* __restrict__ Wx,
                const float* __restrict__ Wn,
                const float* __restrict__ bx,
                const float* __restrict__ bn,
                float* __restrict__ out)
{
    __shared__ float h_s[DD];
    __shared__ float df_s[RR][FF];
    __shared__ __align__(16) float part[RR][8][5][FF];
    __shared__ __align__(16) float red[RR][6][FF];
    __shared__ float rdf_s[RR][FF];
    __shared__ float gru_s[RR][FF];
    __shared__ int   flags[2];

    const int n   = blockIdx.x;
    const int tid = threadIdx.x;
    const int r   = tid >> 7;
    const int wg  = tid & 127;

    if (tid == 0) {
        const int* xi = (const int*)x_raw;
        int idx64 = (xi[1] == 0) ? 1 : 0;
        flags[0] = idx64;
        flags[1] = idx64 ? (int)((const long long*)x_raw)[n] : xi[n];
    }
    __syncthreads();
    const int xn = flags[1];

    if (tid < DD) h_s[tid] = embed[(long long)xn * DD + tid];
    if (wg < FF)  df_s[r][wg] = df_g[((long long)n * RR + r) * FF + wg];
    __syncthreads();

    const long long nr = (long long)n * RR + r;
    const float* Wxr = Wx + nr * (3 * DD * FF);
    const float* Wnr = Wn + nr * (3 * FF * FF);
    const float* bxr = bx + nr * (3 * FF);
    const float* bnr = bn + nr * (3 * FF);

    const int fg = wg & 15;
    const int ds = wg >> 4;
    const int f4 = fg * 4;

    float4 a0 = make_float4(0,0,0,0), a1 = a0, a2v = a0, a3 = a0, a4 = a0;
    #pragma unroll
    for (int dd = 0; dd < 8; dd++) {
        int d = ds * 8 + dd;
        float hd  = h_s[d];
        float dfd = df_s[r][d];
        float4 x0 = __ldg((const float4*)(Wxr + (0*DD + d)*FF + f4));
        float4 x1 = __ldg((const float4*)(Wxr + (1*DD + d)*FF + f4));
        float4 x2 = __ldg((const float4*)(Wxr + (2*DD + d)*FF + f4));
        float4 n0 = __ldg((const float4*)(Wnr + (0*FF + d)*FF + f4));
        float4 n1 = __ldg((const float4*)(Wnr + (1*FF + d)*FF + f4));
        a0.x += hd*x0.x;  a0.y += hd*x0.y;  a0.z += hd*x0.z;  a0.w += hd*x0.w;
        a1.x += hd*x1.x;  a1.y += hd*x1.y;  a1.z += hd*x1.z;  a1.w += hd*x1.w;
        a2v.x+= hd*x2.x;  a2v.y+= hd*x2.y;  a2v.z+= hd*x2.z;  a2v.w+= hd*x2.w;
        a3.x += dfd*n0.x; a3.y += dfd*n0.y; a3.z += dfd*n0.z; a3.w += dfd*n0.w;
        a4.x += dfd*n1.x; a4.y += dfd*n1.y; a4.z += dfd*n1.z; a4.w += dfd*n1.w;
    }
    *(float4*)&part[r][ds][0][f4] = a0;
    *(float4*)&part[r][ds][1][f4] = a1;
    *(float4*)&part[r][ds][2][f4] = a2v;
    *(float4*)&part[r][ds][3][f4] = a3;
    *(float4*)&part[r][ds][4][f4] = a4;
    __syncthreads();

    if (wg < 80) {
        int gate = wg >> 4, fgi = wg & 15;
        float4 s = make_float4(0,0,0,0);
        #pragma unroll
        for (int d2 = 0; d2 < 8; d2++) {
            float4 v = *(const float4*)&part[r][d2][gate][fgi * 4];
            s.x += v.x; s.y += v.y; s.z += v.z; s.w += v.w;
        }
        *(float4*)&red[r][gate][fgi * 4] = s;
    }
    __syncthreads();

    float xh_v = 0.f, z_v = 0.f, dff = 0.f;
    if (wg < FF) {
        int f = wg;
        float xr = red[r][0][f] + __ldg(bxr + f);
        float xz = red[r][1][f] + __ldg(bxr + FF + f);
        xh_v     = red[r][2][f] + __ldg(bxr + 2*FF + f);
        float rg = sigm(xr + red[r][3][f] + __ldg(bnr + f));
        z_v      = sigm(xz + red[r][4][f] + __ldg(bnr + FF + f));
        dff = df_s[r][f];
        rdf_s[r][f] = rg * dff;
    }
    __syncthreads();

    float4 c = make_float4(0,0,0,0);
    #pragma unroll
    for (int dd = 0; dd < 8; dd++) {
        int d = ds * 8 + dd;
        float rd = rdf_s[r][d];
        float4 n2 = __ldg((const float4*)(Wnr + (2*FF + d)*FF + f4));
        c.x += rd*n2.x; c.y += rd*n2.y; c.z += rd*n2.z; c.w += rd*n2.w;
    }
    *(float4*)&part[r][ds][0][f4] = c;
    __syncthreads();

    if (wg < 16) {
        float4 s = make_float4(0,0,0,0);
        #pragma unroll
        for (int d2 = 0; d2 < 8; d2++) {
            float4 v = *(const float4*)&part[r][d2][0][wg * 4];
            s.x += v.x; s.y += v.y; s.z += v.z; s.w += v.w;
        }
        *(float4*)&red[r][5][wg * 4] = s;
    }
    __syncthreads();

    if (wg < FF) {
        float hc = tanhf(xh_v + red[r][5][wg] + __ldg(bnr + 2*FF + wg));
        gru_s[r][wg] = z_v * dff + (1.f - z_v) * hc;
    }
    __syncthreads();

    if (tid < FF)
        out[(long long)n * FF + tid] =
            tanhf(0.5f * (gru_s[0][tid] + gru_s[1][tid]));
}

extern "C" void kernel_launch(void* const* d_in, const int* in_sizes, int n_in,
                              void* d_out, int out_size) {
    (void)in_sizes; (void)n_in; (void)out_size;
    static_assert(ATTN_SMEM_BYTES < 227 * 1024, "smem too big");
    cudaFuncSetAttribute(attn_kernel,
                         cudaFuncAttributeMaxDynamicSharedMemorySize,
                         ATTN_SMEM_BYTES);
    int nsm = 148;
    cudaDeviceGetAttribute(&nsm, cudaDevAttrMultiProcessorCount, 0);
    if (nsm < 1 || nsm > NT) nsm = 148;
    attn_kernel<<<nsm, 256, ATTN_SMEM_BYTES>>>(
        d_in[0], d_in[1],
        (const float*)d_in[2],         // embed
        (const float*)d_in[3],         // w
        (const float*)d_in[4],         // qw
        (const float*)d_in[5]);        // kw
    gru_kernel<<<NN, 256>>>(
        d_in[0],
        (const float*)d_in[2],         // embed
        (const float*)d_in[6],         // Wx
        (const float*)d_in[7],         // Wn
        (const float*)d_in[8],         // bx
        (const float*)d_in[9],         // bn
        (float*)d_out);
}

// round 8
// speedup vs baseline: 1.0323x; 1.0323x over previous
#include <cuda_runtime.h>
#include <cstdint>

// DeepUDI as FOUR gru-shaped streaming kernels (each: tiny load -> 1 barrier
// -> independent bulk stream). This removes the J->Jq->v dependency chain
// that kept the monolithic attention kernel at ~2TB/s.
//   K1a: w stream   -> Hn (scratch), J (scratch)
//   K1b: qw stream  -> Jq (scratch)          [J read is 256B, L2]
//   K1c: kw stream  -> v -> scores -> softmax -> df (scratch)
//   K2 : Wx/Wn stream -> GRU -> out          [unchanged, 76% DRAM]

#define NN   2048
#define RR   2
#define KK   32
#define DD   64
#define FF   64
#define DD2  128
#define HPAD 68
#define NT   (NN * RR)

__device__ float Hn_g[NT * KK * FF];   // 33.5MB
__device__ float J_g [NT * FF];        // 1MB
__device__ float Jq_g[NT * DD2];       // 2MB
__device__ float df_g[NT * FF];        // 1MB

__device__ __forceinline__ float sigm(float v) {
    return 1.f / (1.f + __expf(-v));
}

// ============ K1a: Hn = hn @ w, J = h @ w ==============================
__global__ __launch_bounds__(256)
void k1a_kernel(const void* __restrict__ x_raw,
                const void* __restrict__ nb_raw,
                const float* __restrict__ embed,
                const float* __restrict__ w)
{
    __shared__ __align__(16) float w_s[DD * FF];
    __shared__ __align__(16) float hn_s[KK][HPAD];
    __shared__ float h_s[DD];
    __shared__ int   nb_sh[KK];
    __shared__ int   flags[2];

    const int nr  = blockIdx.x;
    const int n   = nr >> 1;
    const int tid = threadIdx.x;

    // dtype detection (x = arange; int64 view has word[1]==0)
    if (tid == 0) {
        const int* xi = (const int*)x_raw;
        int idx64 = (xi[1] == 0) ? 1 : 0;
        flags[0] = idx64;
        flags[1] = idx64 ? (int)((const long long*)x_raw)[n] : xi[n];
    }
    __syncthreads();
    const int idx64 = flags[0];
    const int xn    = flags[1];

    if (tid < KK) {
        long long base = (long long)nr * KK + tid;
        nb_sh[tid] = idx64 ? (int)((const long long*)nb_raw)[base]
                           : ((const int*)nb_raw)[base];
    }
    if (tid >= 64 && tid < 128)
        h_s[tid - 64] = embed[(long long)xn * DD + (tid - 64)];

    // stream w into smem (16KB, 4 float4/thread, fully independent)
    const float4* ws = (const float4*)(w + (long long)nr * (DD * FF));
    #pragma unroll
    for (int j = 0; j < 4; j++)
        ((float4*)w_s)[tid + 256 * j] = __ldg(ws + tid + 256 * j);
    __syncthreads();

    // gather hn (embed rows, L2-resident 512KB table)
    #pragma unroll
    for (int j = 0; j < 2; j++) {
        int i  = tid + 256 * j;
        int k  = i >> 4, dv = i & 15;
        *(float4*)(&hn_s[k][dv * 4]) =
            *(const float4*)(embed + (long long)nb_sh[k] * DD + dv * 4);
    }
    __syncthreads();

    // Hn: thread = (k, f-octant), 8 accumulators
    const int k  = tid >> 3;
    const int g  = tid & 7;
    const int f0 = g * 8;

    float acc[8];
    #pragma unroll
    for (int j = 0; j < 8; j++) acc[j] = 0.f;

    #pragma unroll 4
    for (int d = 0; d < DD; d++) {
        float a = hn_s[k][d];
        float4 w0 = *(const float4*)&w_s[d * FF + f0];
        float4 w1 = *(const float4*)&w_s[d * FF + f0 + 4];
        acc[0] += a * w0.x; acc[1] += a * w0.y;
        acc[2] += a * w0.z; acc[3] += a * w0.w;
        acc[4] += a * w1.x; acc[5] += a * w1.y;
        acc[6] += a * w1.z; acc[7] += a * w1.w;
    }
    // Hn out: coalesced float4 stores (lane f0 spans rows)
    float* hb = Hn_g + (long long)nr * (KK * FF) + k * FF + f0;
    *(float4*)hb       = make_float4(acc[0], acc[1], acc[2], acc[3]);
    *(float4*)(hb + 4) = make_float4(acc[4], acc[5], acc[6], acc[7]);

    // J = h @ w
    if (tid < FF) {
        float ja = 0.f;
        #pragma unroll 8
        for (int d = 0; d < DD; d++)
            ja += h_s[d] * w_s[d * FF + tid];
        J_g[(long long)nr * FF + tid] = ja;
    }
}

// ============ K1b: Jq = J @ qw =========================================
__global__ __launch_bounds__(256)
void k1b_kernel(const float* __restrict__ qw)
{
    __shared__ float J_s[FF];
    __shared__ float part[2][DD2];

    const int nr  = blockIdx.x;
    const int tid = threadIdx.x;

    if (tid < FF) J_s[tid] = J_g[(long long)nr * FF + tid];
    __syncthreads();

    const int e  = tid & 127;
    const int fh = tid >> 7;
    const float* q = qw + (long long)nr * (FF * DD2) + fh * 32 * DD2 + e;
    float a = 0.f;
    #pragma unroll
    for (int f = 0; f < 32; f++)
        a += J_s[fh * 32 + f] * __ldg(q + f * DD2);
    part[fh][e] = a;
    __syncthreads();

    if (tid < DD2)
        Jq_g[(long long)nr * DD2 + tid] = part[0][tid] + part[1][tid];
}

// ============ K1c: v = kw @ Jq; scores; softmax; df ====================
__global__ __launch_bounds__(256)
void k1c_kernel(const float* __restrict__ kw)
{
    __shared__ __align__(16) float jq_s[DD2];
    __shared__ float v_s[FF];
    __shared__ float sc_s[KK];
    __shared__ __align__(16) float hn_s[KK][HPAD];

    const int nr  = blockIdx.x;
    const int tid = threadIdx.x;
    const int k   = tid >> 3;
    const int g   = tid & 7;
    const int f0  = g * 8;

    if (tid < DD2) jq_s[tid] = Jq_g[(long long)nr * DD2 + tid];

    // Hn tile into regs (independent, coalesced) — also stash in smem for df
    const float* hb = Hn_g + (long long)nr * (KK * FF) + k * FF + f0;
    float4 hA = __ldg((const float4*)hb);
    float4 hB = __ldg((const float4*)(hb + 4));
    *(float4*)&hn_s[k][f0]     = hA;
    *(float4*)&hn_s[k][f0 + 4] = hB;
    __syncthreads();

    // v: 8 warps x 8 rows, float4 lanes, kw streamed coalesced
    {
        const float* kwr = kw + (long long)nr * (FF * DD2);
        int warp = tid >> 5, lane = tid & 31;
        float4 qv = ((const float4*)jq_s)[lane];
        #pragma unroll
        for (int i = 0; i < 8; i++) {
            int f = warp * 8 + i;
            float4 kv = __ldg((const float4*)(kwr + f * DD2) + lane);
            float p = kv.x*qv.x + kv.y*qv.y + kv.z*qv.z + kv.w*qv.w;
            #pragma unroll
            for (int off = 16; off > 0; off >>= 1)
                p += __shfl_xor_sync(0xffffffffu, p, off);
            if (lane == 0) v_s[f] = p;
        }
    }
    __syncthreads();

    // scores from Hn regs
    {
        float s = hA.x*v_s[f0]   + hA.y*v_s[f0+1] + hA.z*v_s[f0+2] + hA.w*v_s[f0+3]
                + hB.x*v_s[f0+4] + hB.y*v_s[f0+5] + hB.z*v_s[f0+6] + hB.w*v_s[f0+7];
        s += __shfl_xor_sync(0xffffffffu, s, 1);
        s += __shfl_xor_sync(0xffffffffu, s, 2);
        s += __shfl_xor_sync(0xffffffffu, s, 4);
        if (g == 0) sc_s[k] = s;
    }
    __syncthreads();

    // softmax over K=32 (warp 0)
    if (tid < 32) {
        float s = sc_s[tid];
        float m = s;
        #pragma unroll
        for (int off = 16; off > 0; off >>= 1)
            m = fmaxf(m, __shfl_xor_sync(0xffffffffu, m, off));
        float e = __expf(s - m);
        float sum = e;
        #pragma unroll
        for (int off = 16; off > 0; off >>= 1)
            sum += __shfl_xor_sync(0xffffffffu, sum, off);
        sc_s[tid] = e / sum;
    }
    __syncthreads();

    // df[f] = sum_k E[k]*Hn[k,f]
    if (tid < FF) {
        float da = 0.f;
        #pragma unroll
        for (int kk = 0; kk < KK; kk++)
            da += sc_s[kk] * hn_s[kk][tid];
        df_g[(long long)nr * FF + tid] = da;
    }
}

// ============ K2: GRU + combine (unchanged, 76% DRAM) ==================
__global__ __launch_bounds__(256)
void gru_kernel(const void* __restrict__ x_raw,
                const float* __restrict__ embed,
                const float* __restrict__ Wx,
                const float* __restrict__ Wn,
                const float* __restrict__ bx,
                const float* __restrict__ bn,
                float* __restrict__ out)
{
    __shared__ float h_s[DD];
    __shared__ float df_s[RR][FF];
    __shared__ __align__(16) float part[RR][8][5][FF];
    __shared__ __align__(16) float red[RR][6][FF];
    __shared__ float rdf_s[RR][FF];
    __shared__ float gru_s[RR][FF];
    __shared__ int   flags[2];

    const int n   = blockIdx.x;
    const int tid = threadIdx.x;
    const int r   = tid >> 7;
    const int wg  = tid & 127;

    if (tid == 0) {
        const int* xi = (const int*)x_raw;
        int idx64 = (xi[1] == 0) ? 1 : 0;
        flags[0] = idx64;
        flags[1] = idx64 ? (int)((const long long*)x_raw)[n] : xi[n];
    }
    __syncthreads();
    const int xn = flags[1];

    if (tid < DD) h_s[tid] = embed[(long long)xn * DD + tid];
    if (wg < FF)  df_s[r][wg] = df_g[((long long)n * RR + r) * FF + wg];
    __syncthreads();

    const long long nr = (long long)n * RR + r;
    const float* Wxr = Wx + nr * (3 * DD * FF);
    const float* Wnr = Wn + nr * (3 * FF * FF);
    const float* bxr = bx + nr * (3 * FF);
    const float* bnr = bn + nr * (3 * FF);

    const int fg = wg & 15;
    const int ds = wg >> 4;
    const int f4 = fg * 4;

    float4 a0 = make_float4(0,0,0,0), a1 = a0, a2v = a0, a3 = a0, a4 = a0;
    #pragma unroll
    for (int dd = 0; dd < 8; dd++) {
        int d = ds * 8 + dd;
        float hd  = h_s[d];
        float dfd = df_s[r][d];
        float4 x0 = __ldg((const float4*)(Wxr + (0*DD + d)*FF + f4));
        float4 x1 = __ldg((const float4*)(Wxr + (1*DD + d)*FF + f4));
        float4 x2 = __ldg((const float4*)(Wxr + (2*DD + d)*FF + f4));
        float4 n0 = __ldg((const float4*)(Wnr + (0*FF + d)*FF + f4));
        float4 n1 = __ldg((const float4*)(Wnr + (1*FF + d)*FF + f4));
        a0.x += hd*x0.x;  a0.y += hd*x0.y;  a0.z += hd*x0.z;  a0.w += hd*x0.w;
        a1.x += hd*x1.x;  a1.y += hd*x1.y;  a1.z += hd*x1.z;  a1.w += hd*x1.w;
        a2v.x+= hd*x2.x;  a2v.y+= hd*x2.y;  a2v.z+= hd*x2.z;  a2v.w+= hd*x2.w;
        a3.x += dfd*n0.x; a3.y += dfd*n0.y; a3.z += dfd*n0.z; a3.w += dfd*n0.w;
        a4.x += dfd*n1.x; a4.y += dfd*n1.y; a4.z += dfd*n1.z; a4.w += dfd*n1.w;
    }
    *(float4*)&part[r][ds][0][f4] = a0;
    *(float4*)&part[r][ds][1][f4] = a1;
    *(float4*)&part[r][ds][2][f4] = a2v;
    *(float4*)&part[r][ds][3][f4] = a3;
    *(float4*)&part[r][ds][4][f4] = a4;
    __syncthreads();

    if (wg < 80) {
        int gate = wg >> 4, fgi = wg & 15;
        float4 s = make_float4(0,0,0,0);
        #pragma unroll
        for (int d2 = 0; d2 < 8; d2++) {
            float4 v = *(const float4*)&part[r][d2][gate][fgi * 4];
            s.x += v.x; s.y += v.y; s.z += v.z; s.w += v.w;
        }
        *(float4*)&red[r][gate][fgi * 4] = s;
    }
    __syncthreads();

    float xh_v = 0.f, z_v = 0.f, dff = 0.f;
    if (wg < FF) {
        int f = wg;
        float xr = red[r][0][f] + __ldg(bxr + f);
        float xz = red[r][1][f] + __ldg(bxr + FF + f);
        xh_v     = red[r][2][f] + __ldg(bxr + 2*FF + f);
        float rg = sigm(xr + red[r][3][f] + __ldg(bnr + f));
        z_v      = sigm(xz + red[r][4][f] + __ldg(bnr + FF + f));
        dff = df_s[r][f];
        rdf_s[r][f] = rg * dff;
    }
    __syncthreads();

    float4 c = make_float4(0,0,0,0);
    #pragma unroll
    for (int dd = 0; dd < 8; dd++) {
        int d = ds * 8 + dd;
        float rd = rdf_s[r][d];
        float4 n2 = __ldg((const float4*)(Wnr + (2*FF + d)*FF + f4));
        c.x += rd*n2.x; c.y += rd*n2.y; c.z += rd*n2.z; c.w += rd*n2.w;
    }
    *(float4*)&part[r][ds][0][f4] = c;
    __syncthreads();

    if (wg < 16) {
        float4 s = make_float4(0,0,0,0);
        #pragma unroll
        for (int d2 = 0; d2 < 8; d2++) {
            float4 v = *(const float4*)&part[r][d2][0][wg * 4];
            s.x += v.x; s.y += v.y; s.z += v.z; s.w += v.w;
        }
        *(float4*)&red[r][5][wg * 4] = s;
    }
    __syncthreads();

    if (wg < FF) {
        float hc = tanhf(xh_v + red[r][5][wg] + __ldg(bnr + 2*FF + wg));
        gru_s[r][wg] = z_v * dff + (1.f - z_v) * hc;
    }
    __syncthreads();

    if (tid < FF)
        out[(long long)n * FF + tid] =
            tanhf(0.5f * (gru_s[0][tid] + gru_s[1][tid]));
}

extern "C" void kernel_launch(void* const* d_in, const int* in_sizes, int n_in,
                              void* d_out, int out_size) {
    (void)in_sizes; (void)n_in; (void)out_size;
    k1a_kernel<<<NT, 256>>>(
        d_in[0], d_in[1],
        (const float*)d_in[2],         // embed
        (const float*)d_in[3]);        // w
    k1b_kernel<<<NT, 256>>>(
        (const float*)d_in[4]);        // qw
    k1c_kernel<<<NT, 256>>>(
        (const float*)d_in[5]);        // kw
    gru_kernel<<<NN, 256>>>(
        d_in[0],
        (const float*)d_in[2],         // embed
        (const float*)d_in[6],         // Wx
        (const float*)d_in[7],         // Wn
        (const float*)d_in[8],         // bx
        (const float*)d_in[9],         // bn
        (float*)d_out);
}